// round 10
// baseline (speedup 1.0000x reference)
#include <cuda_runtime.h>
#include <cuda_bf16.h>
#include <math.h>
#include <stdint.h>

// Problem shape (fixed by reference): B=8, N=2048, E=768
#define BATCH 8
#define SEQ   2048
#define EMB   768
#define ROWS  (BATCH * SEQ)          // 16384

// ---------------------------------------------------------------------------
// Scratch (__device__ globals; no allocations allowed).
// All GEMM operands live as split bf16 (hi, lo) pairs, k-contiguous.
// ---------------------------------------------------------------------------
__device__ __align__(256) __nv_bfloat16 g_xh[ROWS * EMB], g_xl[ROWS * EMB];
__device__ __align__(256) __nv_bfloat16 g_Wqh[EMB * EMB], g_Wql[EMB * EMB];
__device__ __align__(256) __nv_bfloat16 g_Wkh[EMB * EMB], g_Wkl[EMB * EMB];
__device__ __align__(256) __nv_bfloat16 g_Wvh[EMB * EMB], g_Wvl[EMB * EMB];
__device__ __align__(256) __nv_bfloat16 g_Woh[EMB * EMB], g_Wol[EMB * EMB];
__device__ __align__(256) __nv_bfloat16 g_Qh[ROWS * EMB], g_Ql[ROWS * EMB];
__device__ __align__(256) __nv_bfloat16 g_Kh[ROWS * EMB], g_Kl[ROWS * EMB];
__device__ __align__(256) float         g_V [ROWS * EMB];
__device__ __align__(256) __nv_bfloat16 g_Vth[ROWS * EMB], g_Vtl[ROWS * EMB]; // [b][e][s]
__device__ __align__(256) __nv_bfloat16 g_Sh[(size_t)BATCH * SEQ * SEQ];
__device__ __align__(256) __nv_bfloat16 g_Sl[(size_t)BATCH * SEQ * SEQ];
__device__ __align__(256) __nv_bfloat16 g_Oh[ROWS * EMB], g_Ol[ROWS * EMB];

// ---------------------------------------------------------------------------
// Helpers
// ---------------------------------------------------------------------------
__device__ __forceinline__ uint32_t smem_u32(const void* p) {
    uint32_t a;
    asm("{ .reg .u64 t; cvta.to.shared.u64 t, %1; cvt.u32.u64 %0, t; }"
        : "=r"(a) : "l"(p));
    return a;
}

__device__ __forceinline__ void ldsm4(uint32_t* r, uint32_t addr) {
    asm volatile("ldmatrix.sync.aligned.m8n8.x4.shared.b16 {%0,%1,%2,%3}, [%4];"
                 : "=r"(r[0]), "=r"(r[1]), "=r"(r[2]), "=r"(r[3]) : "r"(addr));
}

__device__ __forceinline__ void mma_bf16(float* c, const uint32_t* a,
                                         uint32_t b0, uint32_t b1)
{
    asm volatile(
        "mma.sync.aligned.m16n8k16.row.col.f32.bf16.bf16.f32 "
        "{%0,%1,%2,%3}, {%4,%5,%6,%7}, {%8,%9}, {%0,%1,%2,%3};"
        : "+f"(c[0]), "+f"(c[1]), "+f"(c[2]), "+f"(c[3])
        : "r"(a[0]), "r"(a[1]), "r"(a[2]), "r"(a[3]), "r"(b0), "r"(b1));
}

#define CP_ASYNC16(dst, src) \
    asm volatile("cp.async.cg.shared.global [%0], [%1], 16;" :: "r"(dst), "l"(src))
#define CP_COMMIT() asm volatile("cp.async.commit_group;" ::: "memory")
#define CP_WAIT1()  asm volatile("cp.async.wait_group 1;"  ::: "memory")

__device__ __forceinline__ void split_store2(__nv_bfloat16* Ch, __nv_bfloat16* Cl,
                                             size_t idx, float v0, float v1)
{
    __nv_bfloat162 h = __floats2bfloat162_rn(v0, v1);
    float2 hf = __bfloat1622float2(h);
    __nv_bfloat162 l = __floats2bfloat162_rn(v0 - hf.x, v1 - hf.y);
    *(__nv_bfloat162*)(Ch + idx) = h;
    *(__nv_bfloat162*)(Cl + idx) = l;
}

// ---------------------------------------------------------------------------
// HMMA split-bf16 GEMM.
//   C[M,N] = alpha * A * B^T (+ bias), A:[M,K] k-contig (hi,lo), B:[N,K] k-contig.
//   3-term: Ah*Bh + Ah*Bl + Al*Bh, fp32 accumulate.
// Block tile 256(M) x 128(N), BK=64, 2-stage cp.async pipeline, 512 thr
// (16 warps = 4m x 4n, warp tile 64x32 -> 4 warps/SMSP for latency hiding).
// OUT=0: split bf16 out; OUT=1: fp32 out.
// Smem rows of 128B (64 bf16, k-contig), 16B chunks XOR-swizzled.
// ---------------------------------------------------------------------------
#define TM 256
#define TN 128
#define BKK 64
#define AH_OFF 0
#define AL_OFF 32768
#define BH_OFF 65536
#define BL_OFF 81920
#define STAGE_BYTES 98304
#define GEMM_SMEM  (2 * STAGE_BYTES)     // 192 KB
#define NTHR 512

template<int OUT>
__global__ void __launch_bounds__(NTHR, 1)
gemm_hmma(const __nv_bfloat16* __restrict__ Ah, const __nv_bfloat16* __restrict__ Al,
          int lda, size_t bsA,
          const __nv_bfloat16* __restrict__ Bh, const __nv_bfloat16* __restrict__ Bl,
          int ldb, size_t bsB,
          void* __restrict__ Coh, void* __restrict__ Col,
          int ldc, size_t bsC,
          const float* __restrict__ bias, float alpha, int K)
{
    extern __shared__ char smem[];
    const uint32_t sbase = smem_u32(smem);

    Ah += (size_t)blockIdx.z * bsA;  Al += (size_t)blockIdx.z * bsA;
    Bh += (size_t)blockIdx.z * bsB;  Bl += (size_t)blockIdx.z * bsB;

    const int tid  = threadIdx.x;
    const int lane = tid & 31;
    const int warp = tid >> 5;
    const int wm   = warp >> 2;           // 4 warps in m (64 rows each)
    const int wn   = warp & 3;            // 4 warps in n (32 cols each)
    const int m0   = blockIdx.y * TM;
    const int n0   = blockIdx.x * TN;

    // ---- loader (512 thr):
    //   A: 256 rows; thread t -> row t>>1, part t&1 (0:hi, 1:lo), 8 chunks.
    //   B: 128 rows; thread t -> row t>>2, sub t&3 (hi0-3, hi4-7, lo0-3, lo4-7).
    const int arow  = tid >> 1;
    const int apart = tid & 1;
    const __nv_bfloat16* aSrc = (apart ? Al : Ah) + (size_t)(m0 + arow) * lda;
    const uint32_t aBase = (apart ? AL_OFF : AH_OFF) + (uint32_t)arow * 128;

    const int brow = tid >> 2;
    const int bsub = tid & 3;
    const int bhl  = bsub >> 1;           // 0: hi, 1: lo
    const int bc0  = (bsub & 1) * 4;      // chunk 0..3 or 4..7
    const __nv_bfloat16* bSrc = (bhl ? Bl : Bh) + (size_t)(n0 + brow) * ldb;
    const uint32_t bBase = (bhl ? BL_OFF : BH_OFF) + (uint32_t)brow * 128;

    auto load_stage = [&](int s, int kt) {
        const uint32_t st = sbase + (uint32_t)s * STAGE_BYTES;
        const int ke = kt * BKK;
        #pragma unroll
        for (int c = 0; c < 8; c++) {
            const uint32_t sw = (uint32_t)((c ^ (arow & 7)) << 4);
            CP_ASYNC16(st + aBase + sw, aSrc + ke + c * 8);
        }
        #pragma unroll
        for (int j = 0; j < 4; j++) {
            const int c = bc0 + j;
            const uint32_t sw = (uint32_t)((c ^ (brow & 7)) << 4);
            CP_ASYNC16(st + bBase + sw, bSrc + ke + c * 8);
        }
    };

    // ---- ldmatrix address precompute (mapping validated R7-R9)
    const int g  = lane >> 3;             // 0..3
    const int r8 = lane & 7;
    uint32_t a_ro[4]; int a_sw[4];
    #pragma unroll
    for (int mf = 0; mf < 4; mf++) {
        const int row = wm * 64 + mf * 16 + ((g & 1) << 3) + r8;
        a_ro[mf] = AH_OFF + (uint32_t)row * 128;
        a_sw[mf] = row & 7;
    }
    const int a_ch = g >> 1;              // k8 half for A
    uint32_t b_ro[2]; int b_sw[2];
    #pragma unroll
    for (int nf = 0; nf < 2; nf++) {
        const int row = wn * 32 + nf * 16 + ((g >> 1) << 3) + r8;
        b_ro[nf] = BH_OFF + (uint32_t)row * 128;
        b_sw[nf] = row & 7;
    }
    const int b_ch = g & 1;               // k8 half for B

    float acc[4][4][4];
    #pragma unroll
    for (int i = 0; i < 4; i++)
        #pragma unroll
        for (int j = 0; j < 4; j++)
            #pragma unroll
            for (int k = 0; k < 4; k++) acc[i][j][k] = 0.f;

    const int nK = K / BKK;
    load_stage(0, 0); CP_COMMIT();

    for (int kt = 0; kt < nK; kt++) {
        const int s = kt & 1;
        if (kt + 1 < nK) load_stage(s ^ 1, kt + 1);
        CP_COMMIT();
        CP_WAIT1();
        __syncthreads();

        const uint32_t sa = sbase + (uint32_t)s * STAGE_BYTES;
        #pragma unroll
        for (int kk = 0; kk < 4; kk++) {
            uint32_t ahf[4][4], alf[4][4], bhf[2][4], blf[2][4];
            #pragma unroll
            for (int mf = 0; mf < 4; mf++) {
                const uint32_t ch = (uint32_t)(((kk * 2 + a_ch) ^ a_sw[mf]) << 4);
                ldsm4(ahf[mf], sa + a_ro[mf] + ch);
                ldsm4(alf[mf], sa + a_ro[mf] + 32768u + ch);
            }
            #pragma unroll
            for (int nf = 0; nf < 2; nf++) {
                const uint32_t ch = (uint32_t)(((kk * 2 + b_ch) ^ b_sw[nf]) << 4);
                ldsm4(bhf[nf], sa + b_ro[nf] + ch);
                ldsm4(blf[nf], sa + b_ro[nf] + 16384u + ch);
            }
            #pragma unroll
            for (int mf = 0; mf < 4; mf++) {
                #pragma unroll
                for (int nf = 0; nf < 2; nf++) {
                    #pragma unroll
                    for (int half = 0; half < 2; half++) {
                        float* a = acc[mf][nf * 2 + half];
                        const uint32_t bh0 = bhf[nf][half * 2];
                        const uint32_t bh1 = bhf[nf][half * 2 + 1];
                        mma_bf16(a, ahf[mf], bh0, bh1);                       // hi*hi
                        mma_bf16(a, ahf[mf], blf[nf][half*2], blf[nf][half*2+1]); // hi*lo
                        mma_bf16(a, alf[mf], bh0, bh1);                       // lo*hi
                    }
                }
            }
        }
        __syncthreads();   // stage s free for next overwrite
    }

    // ---- epilogue
    const int mr = lane >> 2;
    const int nc = (lane & 3) * 2;
    #pragma unroll
    for (int mf = 0; mf < 4; mf++) {
        #pragma unroll
        for (int nf = 0; nf < 4; nf++) {
            const int m = m0 + wm * 64 + mf * 16 + mr;
            const int n = n0 + wn * 32 + nf * 8 + nc;
            float b0 = 0.f, b1 = 0.f;
            if (bias) { b0 = bias[n]; b1 = bias[n + 1]; }
            const float v0 = alpha * acc[mf][nf][0] + b0;
            const float v1 = alpha * acc[mf][nf][1] + b1;
            const float v2 = alpha * acc[mf][nf][2] + b0;
            const float v3 = alpha * acc[mf][nf][3] + b1;
            if (OUT == 1) {
                float* C = (float*)Coh + (size_t)blockIdx.z * bsC;
                *(float2*)&C[(size_t)m * ldc + n]       = make_float2(v0, v1);
                *(float2*)&C[(size_t)(m + 8) * ldc + n] = make_float2(v2, v3);
            } else {
                __nv_bfloat16* Ch = (__nv_bfloat16*)Coh + (size_t)blockIdx.z * bsC;
                __nv_bfloat16* Cl = (__nv_bfloat16*)Col + (size_t)blockIdx.z * bsC;
                split_store2(Ch, Cl, (size_t)m * ldc + n, v0, v1);
                split_store2(Ch, Cl, (size_t)(m + 8) * ldc + n, v2, v3);
            }
        }
    }
}

// ---------------------------------------------------------------------------
// Elementwise fp32 -> (hi, lo) bf16 split.
// ---------------------------------------------------------------------------
__global__ void __launch_bounds__(256)
split_f32(const float4* __restrict__ in, __nv_bfloat162* __restrict__ oh,
          __nv_bfloat162* __restrict__ ol, int n4)
{
    const int i = blockIdx.x * 256 + threadIdx.x;
    if (i >= n4) return;
    const float4 v = in[i];
    __nv_bfloat162 h01 = __floats2bfloat162_rn(v.x, v.y);
    __nv_bfloat162 h23 = __floats2bfloat162_rn(v.z, v.w);
    float2 f01 = __bfloat1622float2(h01);
    float2 f23 = __bfloat1622float2(h23);
    oh[2 * i]     = h01;
    oh[2 * i + 1] = h23;
    ol[2 * i]     = __floats2bfloat162_rn(v.x - f01.x, v.y - f01.y);
    ol[2 * i + 1] = __floats2bfloat162_rn(v.z - f23.x, v.w - f23.y);
}

// ---------------------------------------------------------------------------
// Transpose + split: in fp32 [R][C] (batch stride bsIn) -> out bf16 hi/lo [C][R].
// Block (32,8), 32x32 tiles.
// ---------------------------------------------------------------------------
__global__ void __launch_bounds__(256)
transpose_split(const float* __restrict__ in,
                __nv_bfloat16* __restrict__ oh, __nv_bfloat16* __restrict__ ol,
                int R, int C, size_t bsIn, size_t bsOut)
{
    __shared__ float tile[32][33];
    in += (size_t)blockIdx.z * bsIn;
    oh += (size_t)blockIdx.z * bsOut;
    ol += (size_t)blockIdx.z * bsOut;

    const int tx = threadIdx.x, ty = threadIdx.y;
    const int x  = blockIdx.x * 32 + tx;       // col in input
    const int y0 = blockIdx.y * 32;
    #pragma unroll
    for (int j = 0; j < 4; j++)
        tile[ty + j * 8][tx] = in[(size_t)(y0 + ty + j * 8) * C + x];
    __syncthreads();
    #pragma unroll
    for (int j = 0; j < 4; j++) {
        const float v = tile[tx][ty + j * 8];  // = in[y0+tx][bx*32+ty+j*8]
        const __nv_bfloat16 h = __float2bfloat16(v);
        const __nv_bfloat16 l = __float2bfloat16(v - __bfloat162float(h));
        const size_t o = (size_t)(blockIdx.x * 32 + ty + j * 8) * R + y0 + tx;
        oh[o] = h;
        ol[o] = l;
    }
}

// ---------------------------------------------------------------------------
// Softmax over split-bf16 rows (in place): reconstruct hi+lo, softmax fp32,
// write back split. 16384 rows of 2048; 1 block (256 thr) per row.
// ---------------------------------------------------------------------------
__global__ void __launch_bounds__(256)
softmax_split(__nv_bfloat16* __restrict__ Sh, __nv_bfloat16* __restrict__ Sl)
{
    const size_t base = (size_t)blockIdx.x * SEQ;
    __nv_bfloat162* ph = (__nv_bfloat162*)(Sh + base);
    __nv_bfloat162* pl = (__nv_bfloat162*)(Sl + base);
    const int t = threadIdx.x;

    float v[8];
    float m = -1e30f;
    #pragma unroll
    for (int i = 0; i < 4; i++) {
        const float2 hf = __bfloat1622float2(ph[t + i * 256]);
        const float2 lf = __bfloat1622float2(pl[t + i * 256]);
        v[2 * i]     = hf.x + lf.x;
        v[2 * i + 1] = hf.y + lf.y;
        m = fmaxf(m, fmaxf(v[2 * i], v[2 * i + 1]));
    }

    __shared__ float red[8];
    #pragma unroll
    for (int o = 16; o > 0; o >>= 1)
        m = fmaxf(m, __shfl_xor_sync(0xffffffffu, m, o));
    if ((t & 31) == 0) red[t >> 5] = m;
    __syncthreads();
    float mr = red[0];
    #pragma unroll
    for (int i = 1; i < 8; i++) mr = fmaxf(mr, red[i]);
    __syncthreads();

    float sum = 0.f;
    #pragma unroll
    for (int i = 0; i < 8; i++) {
        v[i] = __expf(v[i] - mr);
        sum += v[i];
    }
    #pragma unroll
    for (int o = 16; o > 0; o >>= 1)
        sum += __shfl_xor_sync(0xffffffffu, sum, o);
    if ((t & 31) == 0) red[t >> 5] = sum;
    __syncthreads();
    float sr = 0.f;
    #pragma unroll
    for (int i = 0; i < 8; i++) sr += red[i];
    const float inv = 1.0f / sr;

    #pragma unroll
    for (int i = 0; i < 4; i++) {
        const float p0 = v[2 * i] * inv;
        const float p1 = v[2 * i + 1] * inv;
        const __nv_bfloat162 h = __floats2bfloat162_rn(p0, p1);
        const float2 hf = __bfloat1622float2(h);
        ph[t + i * 256] = h;
        pl[t + i * 256] = __floats2bfloat162_rn(p0 - hf.x, p1 - hf.y);
    }
}

// ---------------------------------------------------------------------------
// Launch.  Inputs: x, Wq, bq, Wk, bk, Wv, bv, Wo, bo.  Output fp32 (8,2048,768)
// NOTE: launch order places a gemm_hmma as the 5th launch so the harness's
// ncu capture (-s 5 -c 1) profiles the GEMM, not a transpose.
// ---------------------------------------------------------------------------
extern "C" void kernel_launch(void* const* d_in, const int* in_sizes, int n_in,
                              void* d_out, int out_size)
{
    const float* x  = (const float*)d_in[0];
    const float* Wq = (const float*)d_in[1];
    const float* bq = (const float*)d_in[2];
    const float* Wk = (const float*)d_in[3];
    const float* bk = (const float*)d_in[4];
    const float* Wv = (const float*)d_in[5];
    const float* bv = (const float*)d_in[6];
    const float* Wo = (const float*)d_in[7];
    const float* bo = (const float*)d_in[8];
    float* out = (float*)d_out;

    __nv_bfloat16 *xh, *xl, *Wqh, *Wql, *Wkh, *Wkl, *Wvh, *Wvl, *Woh, *Wol;
    __nv_bfloat16 *Qh, *Ql, *Kh, *Kl, *Vth, *Vtl, *Sh, *Sl, *Oh, *Ol;
    float* V;
    cudaGetSymbolAddress((void**)&xh,  g_xh);  cudaGetSymbolAddress((void**)&xl,  g_xl);
    cudaGetSymbolAddress((void**)&Wqh, g_Wqh); cudaGetSymbolAddress((void**)&Wql, g_Wql);
    cudaGetSymbolAddress((void**)&Wkh, g_Wkh); cudaGetSymbolAddress((void**)&Wkl, g_Wkl);
    cudaGetSymbolAddress((void**)&Wvh, g_Wvh); cudaGetSymbolAddress((void**)&Wvl, g_Wvl);
    cudaGetSymbolAddress((void**)&Woh, g_Woh); cudaGetSymbolAddress((void**)&Wol, g_Wol);
    cudaGetSymbolAddress((void**)&Qh,  g_Qh);  cudaGetSymbolAddress((void**)&Ql,  g_Ql);
    cudaGetSymbolAddress((void**)&Kh,  g_Kh);  cudaGetSymbolAddress((void**)&Kl,  g_Kl);
    cudaGetSymbolAddress((void**)&V,   g_V);
    cudaGetSymbolAddress((void**)&Vth, g_Vth); cudaGetSymbolAddress((void**)&Vtl, g_Vtl);
    cudaGetSymbolAddress((void**)&Sh,  g_Sh);  cudaGetSymbolAddress((void**)&Sl,  g_Sl);
    cudaGetSymbolAddress((void**)&Oh,  g_Oh);  cudaGetSymbolAddress((void**)&Ol,  g_Ol);

    cudaFuncSetAttribute(gemm_hmma<0>, cudaFuncAttributeMaxDynamicSharedMemorySize, GEMM_SMEM);
    cudaFuncSetAttribute(gemm_hmma<1>, cudaFuncAttributeMaxDynamicSharedMemorySize, GEMM_SMEM);

    const float scale = 1.0f / sqrtf((float)EMB);
    const dim3 tb(32, 8);

    // (1) split x; (2-4) transpose+split Wq/Wk/Wv  (Wo deferred to just before
    // the output projection so launch #5 is a GEMM for ncu)
    split_f32<<<(ROWS * EMB / 4 + 255) / 256, 256>>>(
        (const float4*)x, (__nv_bfloat162*)xh, (__nv_bfloat162*)xl, ROWS * EMB / 4);
    {
        dim3 g(EMB / 32, EMB / 32, 1);
        transpose_split<<<g, tb>>>(Wq, Wqh, Wql, EMB, EMB, 0, 0);
        transpose_split<<<g, tb>>>(Wk, Wkh, Wkl, EMB, EMB, 0, 0);
        transpose_split<<<g, tb>>>(Wv, Wvh, Wvl, EMB, EMB, 0, 0);
    }

    // (5-7) QKV projections (M=16384, N=768, K=768). Q,K -> split; V -> fp32.
    {
        dim3 g(EMB / TN, ROWS / TM, 1);
        gemm_hmma<0><<<g, NTHR, GEMM_SMEM>>>(xh, xl, EMB, 0, Wqh, Wql, EMB, 0,
                                             Qh, Ql, EMB, 0, bq, 1.0f, EMB);
        gemm_hmma<0><<<g, NTHR, GEMM_SMEM>>>(xh, xl, EMB, 0, Wkh, Wkl, EMB, 0,
                                             Kh, Kl, EMB, 0, bk, 1.0f, EMB);
        gemm_hmma<1><<<g, NTHR, GEMM_SMEM>>>(xh, xl, EMB, 0, Wvh, Wvl, EMB, 0,
                                             V, nullptr, EMB, 0, bv, 1.0f, EMB);
    }

    // (8) V transpose+split per batch: [s][e] -> [e][s]
    {
        dim3 g(EMB / 32, SEQ / 32, BATCH);
        transpose_split<<<g, tb>>>(V, Vth, Vtl, SEQ, EMB,
                                   (size_t)SEQ * EMB, (size_t)SEQ * EMB);
    }

    // (9) Scores: S = scale * Q * K^T per batch -> split bf16
    {
        dim3 g(SEQ / TN, SEQ / TM, BATCH);
        gemm_hmma<0><<<g, NTHR, GEMM_SMEM>>>(Qh, Ql, EMB, (size_t)SEQ * EMB,
                                             Kh, Kl, EMB, (size_t)SEQ * EMB,
                                             Sh, Sl, SEQ, (size_t)SEQ * SEQ,
                                             nullptr, scale, EMB);
    }

    // (10) Softmax (in place on split S)
    softmax_split<<<ROWS, 256>>>(Sh, Sl);

    // (11) O = P * V per batch (A = S [q][s], B = Vt [e][s]) -> split bf16
    {
        dim3 g(EMB / TN, SEQ / TM, BATCH);
        gemm_hmma<0><<<g, NTHR, GEMM_SMEM>>>(Sh, Sl, SEQ, (size_t)SEQ * SEQ,
                                             Vth, Vtl, SEQ, (size_t)EMB * SEQ,
                                             Oh, Ol, EMB, (size_t)SEQ * EMB,
                                             nullptr, 1.0f, SEQ);
    }

    // (12) transpose+split Wo; (13) output projection -> d_out (fp32)
    {
        dim3 g(EMB / 32, EMB / 32, 1);
        transpose_split<<<g, tb>>>(Wo, Woh, Wol, EMB, EMB, 0, 0);
    }
    {
        dim3 g(EMB / TN, ROWS / TM, 1);
        gemm_hmma<1><<<g, NTHR, GEMM_SMEM>>>(Oh, Ol, EMB, 0, Woh, Wol, EMB, 0,
                                             out, nullptr, EMB, 0, bo, 1.0f, EMB);
    }
}